// round 4
// baseline (speedup 1.0000x reference)
#include <cuda_runtime.h>
#include <math.h>
#include <stdint.h>

// ---------------------------------------------------------------------------
// Model constants
// ---------------------------------------------------------------------------
#define T_STEPS 800
#define BATCH   128
#define UDIM    64
#define ADIM    64
#define HDIM    256
#define KMIX    10
#define GMIX    20
#define GATES   1024          // 4*H

// Combined GEMV depths: layer1 = [x(3), w(64), h1(256)] = 323
//                       layer2 = [x, w, h1, h2]         = 579
//                       layer3 = [x, w, h2, h3]         = 579
#define K1  323
#define K2  579
#define K3  579
#define K1P 328               // padded to multiple of 8
#define K2P 584
#define K3P 584

#define NB 2                  // batch elements per CTA
#define RNN_THREADS 256
#define RNN_CTAS (BATCH / NB)

#define HEAD_ROWS 32
#define HEAD_THREADS 128
#define TB_ROWS (T_STEPS * BATCH)

// ---------------------------------------------------------------------------
// Device scratch (no allocations allowed -> static __device__ buffers)
// ---------------------------------------------------------------------------
__device__ float g_WT1[K1P * GATES];   // [k][1024] transposed+padded layer1 weights
__device__ float g_WT2[K2P * GATES];
__device__ float g_WT3[K3P * GATES];
__device__ float g_WHt[HDIM * 128];    // head weights [k][o], o padded 121->128
__device__ float g_bh[128];            // head bias
__device__ float g_h3buf[(size_t)T_STEPS * BATCH * HDIM];   // h3 for all (t,b)

// ---------------------------------------------------------------------------
// Prologue: build transposed combined weight matrices
// WT[k][r] = k < IN ? W_ih[r][k] : (k < Ktot ? W_hh[r][k-IN] : 0)
// ---------------------------------------------------------------------------
__global__ void build_wt_kernel(const float* __restrict__ Wih,
                                const float* __restrict__ Whh,
                                int INdim, int Ktot, int Kpad, int which) {
    int idx = blockIdx.x * blockDim.x + threadIdx.x;
    if (idx >= Kpad * GATES) return;
    int k = idx >> 10;        // / 1024
    int r = idx & 1023;
    float v = 0.0f;
    if (k < INdim)      v = Wih[r * INdim + k];
    else if (k < Ktot)  v = Whh[r * HDIM + (k - INdim)];
    float* WT = (which == 0) ? g_WT1 : (which == 1) ? g_WT2 : g_WT3;
    WT[idx] = v;
}

// ---------------------------------------------------------------------------
// Prologue: build head weight matrix [256][128] (k-major, coalesced in o)
// o = 0: We | 1..20: Wpi | 21..40: Wm1 | 41..60: Wm2
// 61..80: Ws1 | 81..100: Ws2 | 101..120: Wr | 121..127: zero pad
// ---------------------------------------------------------------------------
__global__ void build_head_kernel(const float* We,  const float* be,
                                  const float* Wpi, const float* bpi,
                                  const float* Wm1, const float* bm1,
                                  const float* Wm2, const float* bm2,
                                  const float* Ws1, const float* bs1,
                                  const float* Ws2, const float* bs2,
                                  const float* Wr,  const float* br) {
    int idx = blockIdx.x * blockDim.x + threadIdx.x;
    if (idx >= HDIM * 128) return;
    int k = idx >> 7;
    int o = idx & 127;
    const float* W = nullptr; const float* bb = nullptr; int row = 0;
    if (o == 0)        { W = We;  bb = be;  row = 0; }
    else if (o <= 20)  { W = Wpi; bb = bpi; row = o - 1; }
    else if (o <= 40)  { W = Wm1; bb = bm1; row = o - 21; }
    else if (o <= 60)  { W = Wm2; bb = bm2; row = o - 41; }
    else if (o <= 80)  { W = Ws1; bb = bs1; row = o - 61; }
    else if (o <= 100) { W = Ws2; bb = bs2; row = o - 81; }
    else if (o <= 120) { W = Wr;  bb = br;  row = o - 101; }
    g_WHt[k * 128 + o] = W ? W[row * HDIM + k] : 0.0f;
    if (k == 0) g_bh[o] = bb ? bb[row] : 0.0f;
}

// ---------------------------------------------------------------------------
// Recurrent kernel: one CTA per NB=2 batch elements, loops over all T steps.
// ---------------------------------------------------------------------------
struct __align__(16) SmemRNN {
    float cm[NB][UDIM][ADIM];    // attention memory c[b,u,a]      (32 KB)
    float h1[NB][HDIM]; float c1[NB][HDIM];
    float h2[NB][HDIM]; float c2[NB][HDIM];
    float h3[NB][HDIM]; float c3[NB][HDIM];
    float w[NB][ADIM];
    float kappa[NB][16];
    float att[NB][32];           // exp(win): alpha[0..9] beta[10..19] k[20..29]
    float phi[NB][UDIM];
    float vin[NB][592];          // padded combined input vector
    float z[NB][GATES];          // gate pre-activations (also reused as scratch)
};

__device__ __forceinline__ float sigm(float v) { return 1.0f / (1.0f + expf(-v)); }

// z[r] (r = 4*tid .. 4*tid+3) = bias[r] + sum_k WT[k][r] * vin[k], for 2 batches
__device__ __forceinline__ void gemv2b(const float* __restrict__ WT, int Kp,
                                       const float* __restrict__ bias,
                                       const float* __restrict__ v0,
                                       const float* __restrict__ v1,
                                       float* __restrict__ z0,
                                       float* __restrict__ z1) {
    const int tid = threadIdx.x;
    float4 bb = __ldg((const float4*)bias + tid);
    float a00 = bb.x, a01 = bb.y, a02 = bb.z, a03 = bb.w;
    float a10 = bb.x, a11 = bb.y, a12 = bb.z, a13 = bb.w;
    const float4* W4  = (const float4*)WT;
    const float4* v04 = (const float4*)v0;
    const float4* v14 = (const float4*)v1;
    const int nk4 = Kp >> 2;
#pragma unroll 2
    for (int k4 = 0; k4 < nk4; ++k4) {
        float4 x0 = v04[k4];
        float4 x1 = v14[k4];
        const float4* Wp = W4 + ((k4 << 2) << 8) + tid;   // k4*4*256 + tid
        float4 w0 = Wp[0];
        float4 w1 = Wp[256];
        float4 w2 = Wp[512];
        float4 w3 = Wp[768];
        a00 = fmaf(w0.x, x0.x, a00); a01 = fmaf(w0.y, x0.x, a01);
        a02 = fmaf(w0.z, x0.x, a02); a03 = fmaf(w0.w, x0.x, a03);
        a10 = fmaf(w0.x, x1.x, a10); a11 = fmaf(w0.y, x1.x, a11);
        a12 = fmaf(w0.z, x1.x, a12); a13 = fmaf(w0.w, x1.x, a13);

        a00 = fmaf(w1.x, x0.y, a00); a01 = fmaf(w1.y, x0.y, a01);
        a02 = fmaf(w1.z, x0.y, a02); a03 = fmaf(w1.w, x0.y, a03);
        a10 = fmaf(w1.x, x1.y, a10); a11 = fmaf(w1.y, x1.y, a11);
        a12 = fmaf(w1.z, x1.y, a12); a13 = fmaf(w1.w, x1.y, a13);

        a00 = fmaf(w2.x, x0.z, a00); a01 = fmaf(w2.y, x0.z, a01);
        a02 = fmaf(w2.z, x0.z, a02); a03 = fmaf(w2.w, x0.z, a03);
        a10 = fmaf(w2.x, x1.z, a10); a11 = fmaf(w2.y, x1.z, a11);
        a12 = fmaf(w2.z, x1.z, a12); a13 = fmaf(w2.w, x1.z, a13);

        a00 = fmaf(w3.x, x0.w, a00); a01 = fmaf(w3.y, x0.w, a01);
        a02 = fmaf(w3.z, x0.w, a02); a03 = fmaf(w3.w, x0.w, a03);
        a10 = fmaf(w3.x, x1.w, a10); a11 = fmaf(w3.y, x1.w, a11);
        a12 = fmaf(w3.z, x1.w, a12); a13 = fmaf(w3.w, x1.w, a13);
    }
    ((float4*)z0)[tid] = make_float4(a00, a01, a02, a03);
    ((float4*)z1)[tid] = make_float4(a10, a11, a12, a13);
}

__device__ __forceinline__ void cell_update(SmemRNN* s,
                                            float (*h)[HDIM], float (*c)[HDIM]) {
    const int tid = threadIdx.x;
#pragma unroll
    for (int nb = 0; nb < NB; ++nb) {
        float zi = s->z[nb][tid];
        float zf = s->z[nb][tid + 256];
        float zg = s->z[nb][tid + 512];
        float zo = s->z[nb][tid + 768];
        float cc = sigm(zf) * c[nb][tid] + sigm(zi) * tanhf(zg);
        c[nb][tid] = cc;
        h[nb][tid] = sigm(zo) * tanhf(cc);
    }
}

extern __shared__ char smem_raw[];

__global__ void __launch_bounds__(RNN_THREADS, 1)
rnn_kernel(const float* __restrict__ x,    // [T, B, 3]
           const float* __restrict__ cg,   // [B, U, A]
           const float* __restrict__ b1,
           const float* __restrict__ b2,
           const float* __restrict__ b3,
           const float* __restrict__ Ww,   // [30, 256]
           const float* __restrict__ bw)   // [30]
{
    SmemRNN* s = (SmemRNN*)smem_raw;
    const int tid = threadIdx.x;
    const int b0  = blockIdx.x * NB;

    // ---- init state ----
    for (int i = tid; i < NB * UDIM * ADIM; i += RNN_THREADS)
        ((float*)s->cm)[i] = cg[(size_t)b0 * UDIM * ADIM + i];
#pragma unroll
    for (int nb = 0; nb < NB; ++nb) {
        s->h1[nb][tid] = 0.0f; s->c1[nb][tid] = 0.0f;
        s->h2[nb][tid] = 0.0f; s->c2[nb][tid] = 0.0f;
        s->h3[nb][tid] = 0.0f; s->c3[nb][tid] = 0.0f;
        if (tid < ADIM) s->w[nb][tid] = 1.0f;
        if (tid < 16)   s->kappa[nb][tid] = 0.0f;
    }
    __syncthreads();

    for (int t = 0; t < T_STEPS; ++t) {
        const float* xt = x + ((size_t)t * BATCH + b0) * 3;

        // ---- build vin for layer 1: [x(3), w(64), h1(256)], pad to K1P ----
#pragma unroll
        for (int nb = 0; nb < NB; ++nb) {
            for (int i = tid; i < K1P; i += RNN_THREADS) {
                float v;
                if (i < 3)        v = xt[nb * 3 + i];
                else if (i < 67)  v = s->w[nb][i - 3];
                else if (i < K1)  v = s->h1[nb][i - 67];
                else              v = 0.0f;
                s->vin[nb][i] = v;
            }
        }
        __syncthreads();
        gemv2b(g_WT1, K1P, b1, s->vin[0], s->vin[1], s->z[0], s->z[1]);
        __syncthreads();
        cell_update(s, s->h1, s->c1);
        __syncthreads();

        // ---- attention window ----
        // partial dots: 60 outputs (2 batches x 30), 4 threads each
        {
            float* red = &s->z[0][0];   // scratch (z no longer needed)
            if (tid < 240) {
                int g   = tid >> 2;        // 0..59
                int sub = tid & 3;
                int nb  = g / 30;
                int o   = g % 30;
                const float* wr = Ww + o * HDIM + sub * 64;
                const float* hv = &s->h1[nb][sub * 64];
                float acc = 0.0f;
#pragma unroll 8
                for (int k = 0; k < 64; ++k) acc = fmaf(__ldg(&wr[k]), hv[k], acc);
                red[tid] = acc;
            }
            __syncthreads();
            if (tid < 60) {
                int nb = tid / 30, o = tid % 30;
                float v = red[4 * tid] + red[4 * tid + 1] +
                          red[4 * tid + 2] + red[4 * tid + 3] + __ldg(&bw[o]);
                s->att[nb][o] = expf(v);
            }
            __syncthreads();
            if (tid < NB * KMIX) {
                int nb = tid / KMIX, kk = tid % KMIX;
                s->kappa[nb][kk] += 0.1f * s->att[nb][20 + kk];
            }
            __syncthreads();
            if (tid < NB * UDIM) {
                int nb = tid >> 6, u = tid & 63;
                float uu = (float)u;
                float acc = 0.0f;
#pragma unroll
                for (int kk = 0; kk < KMIX; ++kk) {
                    float d = s->kappa[nb][kk] - uu;
                    acc = fmaf(s->att[nb][kk], expf(-s->att[nb][10 + kk] * d * d), acc);
                }
                s->phi[nb][u] = acc;
            }
            __syncthreads();
            if (tid < NB * ADIM) {
                int nb = tid >> 6, a = tid & 63;
                float acc = 0.0f;
#pragma unroll 8
                for (int u = 0; u < UDIM; ++u)
                    acc = fmaf(s->phi[nb][u], s->cm[nb][u][a], acc);
                s->w[nb][a] = acc;
            }
            __syncthreads();
        }

        // ---- layer 2: vin = [x, w, h1, h2], pad to K2P ----
#pragma unroll
        for (int nb = 0; nb < NB; ++nb) {
            for (int i = tid; i < K2P; i += RNN_THREADS) {
                float v;
                if (i < 3)        v = xt[nb * 3 + i];
                else if (i < 67)  v = s->w[nb][i - 3];
                else if (i < 323) v = s->h1[nb][i - 67];
                else if (i < K2)  v = s->h2[nb][i - 323];
                else              v = 0.0f;
                s->vin[nb][i] = v;
            }
        }
        __syncthreads();
        gemv2b(g_WT2, K2P, b2, s->vin[0], s->vin[1], s->z[0], s->z[1]);
        __syncthreads();
        cell_update(s, s->h2, s->c2);
        __syncthreads();

        // ---- layer 3: vin = [x, w, h2, h3], pad to K3P ----
#pragma unroll
        for (int nb = 0; nb < NB; ++nb) {
            for (int i = tid; i < K3P; i += RNN_THREADS) {
                float v;
                if (i < 3)        v = xt[nb * 3 + i];
                else if (i < 67)  v = s->w[nb][i - 3];
                else if (i < 323) v = s->h2[nb][i - 67];
                else if (i < K3)  v = s->h3[nb][i - 323];
                else              v = 0.0f;
                s->vin[nb][i] = v;
            }
        }
        __syncthreads();
        gemv2b(g_WT3, K3P, b3, s->vin[0], s->vin[1], s->z[0], s->z[1]);
        __syncthreads();
        cell_update(s, s->h3, s->c3);
        __syncthreads();

        // ---- stream h3 to global for the output head ----
#pragma unroll
        for (int nb = 0; nb < NB; ++nb)
            g_h3buf[((size_t)t * BATCH + b0 + nb) * HDIM + tid] = s->h3[nb][tid];
        // no sync needed: next phase writes only vin/x (different buffers)
        __syncthreads();
    }
}

// ---------------------------------------------------------------------------
// Output head: out[row][o] = act(h3[row] . WHt[:,o] + bh[o])
// out layout: es[TB] | pis[TB*G] | mu1[TB*G] | mu2[TB*G] | s1[TB*G] | s2[TB*G] | rho[TB*G]
// ---------------------------------------------------------------------------
__global__ void __launch_bounds__(HEAD_THREADS)
head_kernel(float* __restrict__ out) {
    __shared__ float sh[HEAD_ROWS * HDIM];   // 32 KB; reused as so[32][129] later
    const int tid = threadIdx.x;
    const int r0  = blockIdx.x * HEAD_ROWS;

    for (int i = tid; i < HEAD_ROWS * HDIM; i += HEAD_THREADS)
        sh[i] = g_h3buf[(size_t)r0 * HDIM + i];
    __syncthreads();

    float acc[HEAD_ROWS];
    float bias = g_bh[tid];
#pragma unroll
    for (int r = 0; r < HEAD_ROWS; ++r) acc[r] = bias;

    for (int k = 0; k < HDIM; k += 4) {
        float w0 = g_WHt[(k + 0) * 128 + tid];
        float w1 = g_WHt[(k + 1) * 128 + tid];
        float w2 = g_WHt[(k + 2) * 128 + tid];
        float w3 = g_WHt[(k + 3) * 128 + tid];
#pragma unroll
        for (int r = 0; r < HEAD_ROWS; ++r) {
            float4 hv = *(const float4*)&sh[r * HDIM + k];
            acc[r] = fmaf(hv.x, w0, fmaf(hv.y, w1, fmaf(hv.z, w2, fmaf(hv.w, w3, acc[r]))));
        }
    }
    __syncthreads();           // done reading sh -> reuse as so[32][129]

    float* so = sh;
    if (tid < 121) {
#pragma unroll
        for (int r = 0; r < HEAD_ROWS; ++r) so[r * 129 + tid] = acc[r];
    }
    __syncthreads();

    // softmax over the 20 pi logits (cols 1..20), one thread per row
    if (tid < HEAD_ROWS) {
        float m = -1e30f;
#pragma unroll
        for (int g = 0; g < GMIX; ++g) m = fmaxf(m, so[tid * 129 + 1 + g]);
        float e[GMIX]; float ssum = 0.0f;
#pragma unroll
        for (int g = 0; g < GMIX; ++g) { e[g] = expf(so[tid * 129 + 1 + g] - m); ssum += e[g]; }
        float inv = 1.0f / ssum;
#pragma unroll
        for (int g = 0; g < GMIX; ++g) so[tid * 129 + 1 + g] = e[g] * inv;
    }
    __syncthreads();

    const size_t TB  = (size_t)TB_ROWS;
    const size_t TBG = TB * GMIX;
    float* es  = out;
    float* pis = out + TB;
    float* mu1 = pis + TBG;
    float* mu2 = mu1 + TBG;
    float* s1  = mu2 + TBG;
    float* s2  = s1 + TBG;
    float* rho = s2 + TBG;

    if (tid < HEAD_ROWS)
        es[r0 + tid] = 1.0f / (1.0f + expf(so[tid * 129 + 0]));   // sigmoid(-z)

    for (int idx = tid; idx < HEAD_ROWS * GMIX; idx += HEAD_THREADS) {
        int r = idx / GMIX, g = idx % GMIX;
        size_t off = (size_t)(r0 + r) * GMIX + g;
        pis[off] = so[r * 129 + 1 + g];
        mu1[off] = so[r * 129 + 21 + g];
        mu2[off] = so[r * 129 + 41 + g];
        s1[off]  = expf(so[r * 129 + 61 + g]);
        s2[off]  = expf(so[r * 129 + 81 + g]);
        rho[off] = tanhf(so[r * 129 + 101 + g]);
    }
}

// ---------------------------------------------------------------------------
// Launch
// ---------------------------------------------------------------------------
extern "C" void kernel_launch(void* const* d_in, const int* in_sizes, int n_in,
                              void* d_out, int out_size) {
    (void)in_sizes; (void)n_in; (void)out_size;
    const float* x     = (const float*)d_in[0];
    const float* cg    = (const float*)d_in[1];
    const float* W1ih  = (const float*)d_in[2];
    const float* W1hh  = (const float*)d_in[3];
    const float* b1    = (const float*)d_in[4];
    const float* W2ih  = (const float*)d_in[5];
    const float* W2hh  = (const float*)d_in[6];
    const float* b2    = (const float*)d_in[7];
    const float* W3ih  = (const float*)d_in[8];
    const float* W3hh  = (const float*)d_in[9];
    const float* b3    = (const float*)d_in[10];
    const float* Ww    = (const float*)d_in[11];
    const float* bw    = (const float*)d_in[12];
    const float* We    = (const float*)d_in[13];
    const float* be    = (const float*)d_in[14];
    const float* Wpi   = (const float*)d_in[15];
    const float* bpi   = (const float*)d_in[16];
    const float* Wm1   = (const float*)d_in[17];
    const float* bm1   = (const float*)d_in[18];
    const float* Wm2   = (const float*)d_in[19];
    const float* bm2   = (const float*)d_in[20];
    const float* Ws1   = (const float*)d_in[21];
    const float* bs1   = (const float*)d_in[22];
    const float* Ws2   = (const float*)d_in[23];
    const float* bs2   = (const float*)d_in[24];
    const float* Wr    = (const float*)d_in[25];
    const float* br    = (const float*)d_in[26];

    // prologue: weight transposes
    build_wt_kernel<<<(K1P * GATES + 255) / 256, 256>>>(W1ih, W1hh, 3 + ADIM, K1, K1P, 0);
    build_wt_kernel<<<(K2P * GATES + 255) / 256, 256>>>(W2ih, W2hh, 3 + ADIM + HDIM, K2, K2P, 1);
    build_wt_kernel<<<(K3P * GATES + 255) / 256, 256>>>(W3ih, W3hh, 3 + ADIM + HDIM, K3, K3P, 2);
    build_head_kernel<<<(HDIM * 128 + 255) / 256, 256>>>(We, be, Wpi, bpi, Wm1, bm1,
                                                         Wm2, bm2, Ws1, bs1, Ws2, bs2, Wr, br);

    // recurrent kernel
    static bool attr_set = false;
    int smem_bytes = (int)sizeof(SmemRNN);
    if (!attr_set) {
        cudaFuncSetAttribute(rnn_kernel, cudaFuncAttributeMaxDynamicSharedMemorySize,
                             smem_bytes);
        attr_set = true;
    }
    rnn_kernel<<<RNN_CTAS, RNN_THREADS, smem_bytes>>>(x, cg, b1, b2, b3, Ww, bw);

    // output head
    head_kernel<<<TB_ROWS / HEAD_ROWS, HEAD_THREADS>>>((float*)d_out);
}

// round 5
// speedup vs baseline: 1.2646x; 1.2646x over previous
#include <cuda_runtime.h>
#include <math.h>
#include <stdint.h>

// ---------------------------------------------------------------------------
// Model constants
// ---------------------------------------------------------------------------
#define T_STEPS 800
#define BATCH   128
#define UDIM    64
#define ADIM    64
#define HDIM    256
#define KMIX    10
#define GMIX    20

#define K1  323               // layer1 gemv depth: x(3)+w(64)+h1(256)
#define K23 579               // layer2/3 depth:    x(3)+w(64)+h(256)+h(256)
#define NK4_1  88             // k4 count, padded: 88*4 = 352 >= 323
#define NK4_23 152            // 152*4 = 608 >= 579
#define KP1  (NK4_1 * 4)      // 352
#define KP23 (NK4_23 * 4)     // 608

#define NSLICE  8             // gate slices per batch group
#define NBATCH  8             // batches per group
#define NGROUPS (BATCH / NBATCH)   // 16
#define UNITS   32            // hidden units per slice
#define ROWS    128           // gate rows per slice (4 gates x 32 units)
#define RNN_THREADS 256
#define RNN_CTAS (NGROUPS * NSLICE)   // 128 (one wave, all co-resident)

#define HEAD_ROWS 32
#define HEAD_THREADS 128
#define TB_ROWS (T_STEPS * BATCH)

// ---------------------------------------------------------------------------
// Device scratch (static __device__ — no allocations allowed)
// ---------------------------------------------------------------------------
__device__ float g_W1[NSLICE * NK4_1  * 512];   // [slice][k4][row m][4 kk]
__device__ float g_W2[NSLICE * NK4_23 * 512];
__device__ float g_W3[NSLICE * NK4_23 * 512];
__device__ float g_B[3 * NSLICE * 128];         // sliced biases
__device__ float g_hx[NGROUPS][3][HDIM][NBATCH];   // h exchange buffers
__device__ float g_wx[NGROUPS][ADIM][NBATCH];      // attention-w exchange
__device__ int   g_flags[NGROUPS * T_STEPS * 4];   // group-barrier flags
__device__ float g_WHt[HDIM * 128];             // head weights [k][o]
__device__ float g_bh[128];
__device__ float g_h3buf[(size_t)T_STEPS * BATCH * HDIM];

// ---------------------------------------------------------------------------
// Prologue kernels
// ---------------------------------------------------------------------------
__global__ void zero_flags_kernel() {
    int i = blockIdx.x * blockDim.x + threadIdx.x;
    if (i < NGROUPS * T_STEPS * 4) g_flags[i] = 0;
}

// Sliced, transposed, k4-blocked weights:
// dest[r][k4][m][kk] = W_combined[row][k],  row = (m>>5)*256 + r*32 + (m&31),
// k = 4*k4+kk;  W_combined = [W_ih | W_hh | zero-pad] along k.
__global__ void build_ws_kernel(const float* __restrict__ Wih,
                                const float* __restrict__ Whh,
                                int INdim, int Ktot, int nk4, int layer) {
    int idx = blockIdx.x * blockDim.x + threadIdx.x;
    int per = nk4 * 512;
    if (idx >= NSLICE * per) return;
    int r   = idx / per;
    int rem = idx % per;
    int k4  = rem >> 9;
    int q   = rem & 511;
    int m   = q >> 2;
    int kk  = q & 3;
    int k   = k4 * 4 + kk;
    int row = (m >> 5) * 256 + r * UNITS + (m & 31);
    float v = 0.0f;
    if (k < INdim)      v = Wih[row * INdim + k];
    else if (k < Ktot)  v = Whh[row * HDIM + (k - INdim)];
    float* dst = (layer == 0) ? g_W1 : (layer == 1) ? g_W2 : g_W3;
    dst[idx] = v;
}

__global__ void build_bias_kernel(const float* b1, const float* b2, const float* b3) {
    int idx = blockIdx.x * blockDim.x + threadIdx.x;
    if (idx >= 3 * NSLICE * 128) return;
    int layer = idx / (NSLICE * 128);
    int rem   = idx % (NSLICE * 128);
    int r     = rem / 128;
    int m     = rem % 128;
    int row   = (m >> 5) * 256 + r * UNITS + (m & 31);
    const float* b = (layer == 0) ? b1 : (layer == 1) ? b2 : b3;
    g_B[idx] = b[row];
}

__global__ void build_head_kernel(const float* We,  const float* be,
                                  const float* Wpi, const float* bpi,
                                  const float* Wm1, const float* bm1,
                                  const float* Wm2, const float* bm2,
                                  const float* Ws1, const float* bs1,
                                  const float* Ws2, const float* bs2,
                                  const float* Wr,  const float* br) {
    int idx = blockIdx.x * blockDim.x + threadIdx.x;
    if (idx >= HDIM * 128) return;
    int k = idx >> 7;
    int o = idx & 127;
    const float* W = nullptr; const float* bb = nullptr; int row = 0;
    if (o == 0)        { W = We;  bb = be;  row = 0; }
    else if (o <= 20)  { W = Wpi; bb = bpi; row = o - 1; }
    else if (o <= 40)  { W = Wm1; bb = bm1; row = o - 21; }
    else if (o <= 60)  { W = Wm2; bb = bm2; row = o - 41; }
    else if (o <= 80)  { W = Ws1; bb = bs1; row = o - 61; }
    else if (o <= 100) { W = Ws2; bb = bs2; row = o - 81; }
    else if (o <= 120) { W = Wr;  bb = br;  row = o - 101; }
    g_WHt[k * 128 + o] = W ? W[row * HDIM + k] : 0.0f;
    if (k == 0) g_bh[o] = bb ? bb[row] : 0.0f;
}

// ---------------------------------------------------------------------------
// Recurrent kernel: 128 CTAs (16 groups x 8 slices), persistent over T steps
// ---------------------------------------------------------------------------
#define WW_STRIDE 268          // padded Ww^T row stride (floats), conflict-free f4
#define H1T_STRIDE 260         // padded h1 copy stride

struct __align__(16) SmemR {
    float vin1[KP1  * NBATCH];   // [k][b]
    float vin2[KP23 * NBATCH];
    float vin3[KP23 * NBATCH];
    float z[NBATCH * 128];       // [b][m]
    float c1[UNITS * NBATCH];    // [u*8+b]
    float c2[UNITS * NBATCH];
    float c3[UNITS * NBATCH];
    float cm[UDIM * 64];         // [u][b*8+a] (a = local a within slice)
    float Wws[30 * WW_STRIDE];   // attention weights, row-major per o, padded
    float h1t[NBATCH * H1T_STRIDE]; // h1 full copy [b][k] for win dot
    float bws[32];
    float b1s[128], b2s[128], b3s[128];
    float atts[32 * NBATCH];     // exp(win): [o*8+b]
    float kappas[KMIX * NBATCH]; // [kk*8+b]
    float phis[UDIM * NBATCH];   // [u*8+b]
};

__device__ __forceinline__ float sigm(float v) { return 1.0f / (1.0f + __expf(-v)); }

// group barrier: all 8 slice-CTAs of a group rendezvous at (t, site)
__device__ __forceinline__ void group_barrier(int g, int t, int site) {
    __threadfence();            // make this CTA's global writes visible
    __syncthreads();
    if (threadIdx.x == 0) {
        int* f = &g_flags[((g * T_STEPS) + t) * 4 + site];
        atomicAdd(f, 1);
        while (*((volatile int*)f) < NSLICE) { }
    }
    __syncthreads();
}

// z[b][m] = bias[m] + sum_k W[k][m] * vin[k][b]   (this CTA's 128-row slice)
__device__ __forceinline__ void gemv_slice(const float* __restrict__ W,
                                           const float* __restrict__ bias,
                                           const float* __restrict__ vin,
                                           float* __restrict__ z_s, int nk4) {
    const int tid  = threadIdx.x;
    const int m    = tid >> 1;
    const int half = tid & 1;
    const float4* W4 = (const float4*)W;          // [k4*128 + m]
    const float4* V4 = ((const float4*)vin) + half;  // [k*2 + half]
    float b = bias[m];
    float a0 = b, a1 = b, a2 = b, a3 = b;
    for (int kb = 0; kb < nk4; kb += 8) {
        float4 w[8];
#pragma unroll
        for (int j = 0; j < 8; ++j) w[j] = W4[(kb + j) * 128 + m];
#pragma unroll
        for (int j = 0; j < 8; ++j) {
            const float4* vp = V4 + ((kb + j) << 3);
            float4 v0 = vp[0], v1 = vp[2], v2 = vp[4], v3 = vp[6];
            float4 wj = w[j];
            a0 = fmaf(wj.x, v0.x, a0); a1 = fmaf(wj.x, v0.y, a1);
            a2 = fmaf(wj.x, v0.z, a2); a3 = fmaf(wj.x, v0.w, a3);
            a0 = fmaf(wj.y, v1.x, a0); a1 = fmaf(wj.y, v1.y, a1);
            a2 = fmaf(wj.y, v1.z, a2); a3 = fmaf(wj.y, v1.w, a3);
            a0 = fmaf(wj.z, v2.x, a0); a1 = fmaf(wj.z, v2.y, a1);
            a2 = fmaf(wj.z, v2.z, a2); a3 = fmaf(wj.z, v2.w, a3);
            a0 = fmaf(wj.w, v3.x, a0); a1 = fmaf(wj.w, v3.y, a1);
            a2 = fmaf(wj.w, v3.z, a2); a3 = fmaf(wj.w, v3.w, a3);
        }
    }
    z_s[(half * 4 + 0) * 128 + m] = a0;
    z_s[(half * 4 + 1) * 128 + m] = a1;
    z_s[(half * 4 + 2) * 128 + m] = a2;
    z_s[(half * 4 + 3) * 128 + m] = a3;
}

// LSTM cell for this slice's 32 units x 8 batches; publishes h slice to global
__device__ __forceinline__ float cell_update(const float* __restrict__ z_s,
                                             float* __restrict__ c_s,
                                             float (*hx)[NBATCH], int r) {
    const int tid = threadIdx.x;
    const int u = tid >> 3, b = tid & 7;
    float zi = z_s[b * 128 +  0 + u];
    float zf = z_s[b * 128 + 32 + u];
    float zg = z_s[b * 128 + 64 + u];
    float zo = z_s[b * 128 + 96 + u];
    float c  = sigm(zf) * c_s[tid] + sigm(zi) * tanhf(zg);
    c_s[tid] = c;
    float h  = sigm(zo) * tanhf(c);
    hx[r * UNITS + u][b] = h;
    return h;
}

extern __shared__ char smem_raw[];

__global__ void __launch_bounds__(RNN_THREADS, 1)
rnn_kernel(const float* __restrict__ x,    // [T, B, 3]
           const float* __restrict__ cg,   // [B, U, A]
           const float* __restrict__ Ww,   // [30, 256]
           const float* __restrict__ bw)   // [30]
{
    SmemR* s = (SmemR*)smem_raw;
    const int tid = threadIdx.x;
    const int g   = blockIdx.x >> 3;     // batch group 0..15
    const int r   = blockIdx.x & 7;      // gate slice  0..7
    const int b0  = g * NBATCH;

    // ---- init ----
    for (int i = tid; i < 30 * 256; i += RNN_THREADS) {
        int o = i >> 8, k = i & 255;
        s->Wws[o * WW_STRIDE + k] = Ww[o * 256 + k];
    }
    if (tid < 32) s->bws[tid] = (tid < 30) ? bw[tid] : 0.0f;
    if (tid < 128) {
        s->b1s[tid] = g_B[(0 * NSLICE + r) * 128 + tid];
        s->b2s[tid] = g_B[(1 * NSLICE + r) * 128 + tid];
        s->b3s[tid] = g_B[(2 * NSLICE + r) * 128 + tid];
    }
    for (int i = tid; i < UDIM * 64; i += RNN_THREADS) {
        int u = i >> 6, q = i & 63, b = q >> 3, a = q & 7;
        s->cm[i] = cg[(size_t)(b0 + b) * (UDIM * ADIM) + u * ADIM + (r * 8 + a)];
    }
    for (int i = tid; i < KP1 * NBATCH; i += RNN_THREADS) s->vin1[i] = 0.0f;
    for (int i = tid; i < KP23 * NBATCH; i += RNN_THREADS) { s->vin2[i] = 0.0f; s->vin3[i] = 0.0f; }
    __syncthreads();
    // w init = 1 (slots k=3..66)
    for (int i = tid; i < ADIM * NBATCH; i += RNN_THREADS) {
        s->vin1[24 + i] = 1.0f; s->vin2[24 + i] = 1.0f; s->vin3[24 + i] = 1.0f;
    }
    s->c1[tid] = 0.0f; s->c2[tid] = 0.0f; s->c3[tid] = 0.0f;
    if (tid < KMIX * NBATCH) s->kappas[tid] = 0.0f;
    __syncthreads();

    const float* W1 = g_W1 + r * (NK4_1  * 512);
    const float* W2 = g_W2 + r * (NK4_23 * 512);
    const float* W3 = g_W3 + r * (NK4_23 * 512);

    for (int t = 0; t < T_STEPS; ++t) {
        // ---- x(t) into all three vins ----
        if (tid < 24) {
            int b = tid / 3, k = tid % 3;
            float xv = x[((size_t)t * BATCH + b0 + b) * 3 + k];
            s->vin1[k * 8 + b] = xv; s->vin2[k * 8 + b] = xv; s->vin3[k * 8 + b] = xv;
        }
        __syncthreads();

        // ---- layer 1 ----
        gemv_slice(W1, s->b1s, s->vin1, s->z, NK4_1);
        __syncthreads();
        cell_update(s->z, s->c1, g_hx[g][0], r);
        group_barrier(g, t, 0);
        for (int i = tid; i < HDIM * NBATCH; i += RNN_THREADS) {
            int u = i >> 3, b = i & 7;
            float h = __ldcg(&g_hx[g][0][u][b]);
            s->vin1[536 + i] = h;           // (67+u)*8+b
            s->vin2[536 + i] = h;
            s->h1t[b * H1T_STRIDE + u] = h; // [b][k] for win dot
        }
        __syncthreads();

        // ---- attention window (win/kappa/phi replicated; w sliced by a) ----
        if (tid < 240) {
            int o = tid >> 3, b = tid & 7;
            const float4* wr = (const float4*)(s->Wws + o * WW_STRIDE);
            const float4* hv = (const float4*)(s->h1t + b * H1T_STRIDE);
            float acc = s->bws[o];
#pragma unroll 4
            for (int k4 = 0; k4 < 64; ++k4) {
                float4 wv = wr[k4], hh = hv[k4];
                acc = fmaf(wv.x, hh.x, acc); acc = fmaf(wv.y, hh.y, acc);
                acc = fmaf(wv.z, hh.z, acc); acc = fmaf(wv.w, hh.w, acc);
            }
            s->atts[o * 8 + b] = __expf(acc);
        }
        __syncthreads();
        if (tid < KMIX * NBATCH) {
            int kk = tid >> 3, b = tid & 7;
            s->kappas[tid] += 0.1f * s->atts[(20 + kk) * 8 + b];
        }
        __syncthreads();
        for (int i = tid; i < UDIM * NBATCH; i += RNN_THREADS) {
            int u = i >> 3, b = i & 7;
            float uu = (float)u;
            float acc = 0.0f;
#pragma unroll
            for (int kk = 0; kk < KMIX; ++kk) {
                float d = s->kappas[kk * 8 + b] - uu;
                acc = fmaf(s->atts[kk * 8 + b],
                           __expf(-s->atts[(10 + kk) * 8 + b] * d * d), acc);
            }
            s->phis[i] = acc;
        }
        __syncthreads();
        if (tid < 64) {    // w[b][a_local] for this slice's a range
            int b = tid >> 3, a = tid & 7;
            float acc = 0.0f;
#pragma unroll 8
            for (int u = 0; u < UDIM; ++u)
                acc = fmaf(s->phis[u * 8 + b], s->cm[u * 64 + b * 8 + a], acc);
            g_wx[g][r * 8 + a][b] = acc;
        }
        group_barrier(g, t, 1);
        for (int i = tid; i < ADIM * NBATCH; i += RNN_THREADS) {
            int a = i >> 3, b = i & 7;
            float wv = __ldcg(&g_wx[g][a][b]);
            s->vin1[24 + i] = wv; s->vin2[24 + i] = wv; s->vin3[24 + i] = wv;
        }
        __syncthreads();

        // ---- layer 2 ----
        gemv_slice(W2, s->b2s, s->vin2, s->z, NK4_23);
        __syncthreads();
        cell_update(s->z, s->c2, g_hx[g][1], r);
        group_barrier(g, t, 2);
        for (int i = tid; i < HDIM * NBATCH; i += RNN_THREADS) {
            float h = __ldcg(&g_hx[g][1][i >> 3][i & 7]);
            s->vin3[536 + i]  = h;    // h2 at k=67.. in vin3
            s->vin2[2584 + i] = h;    // h2 at k=323.. in vin2 (recurrent)
        }
        __syncthreads();

        // ---- layer 3 ----
        gemv_slice(W3, s->b3s, s->vin3, s->z, NK4_23);
        __syncthreads();
        {
            float h = cell_update(s->z, s->c3, g_hx[g][2], r);
            int u = tid >> 3, b = tid & 7;
            g_h3buf[((size_t)t * BATCH + b0 + b) * HDIM + r * UNITS + u] = h;
        }
        group_barrier(g, t, 3);
        for (int i = tid; i < HDIM * NBATCH; i += RNN_THREADS)
            s->vin3[2584 + i] = __ldcg(&g_hx[g][2][i >> 3][i & 7]);
        __syncthreads();
    }
}

// ---------------------------------------------------------------------------
// Output head (unchanged from passing version)
// ---------------------------------------------------------------------------
__global__ void __launch_bounds__(HEAD_THREADS)
head_kernel(float* __restrict__ out) {
    __shared__ float sh[HEAD_ROWS * HDIM];
    const int tid = threadIdx.x;
    const int r0  = blockIdx.x * HEAD_ROWS;

    for (int i = tid; i < HEAD_ROWS * HDIM; i += HEAD_THREADS)
        sh[i] = g_h3buf[(size_t)r0 * HDIM + i];
    __syncthreads();

    float acc[HEAD_ROWS];
    float bias = g_bh[tid];
#pragma unroll
    for (int r = 0; r < HEAD_ROWS; ++r) acc[r] = bias;

    for (int k = 0; k < HDIM; k += 4) {
        float w0 = g_WHt[(k + 0) * 128 + tid];
        float w1 = g_WHt[(k + 1) * 128 + tid];
        float w2 = g_WHt[(k + 2) * 128 + tid];
        float w3 = g_WHt[(k + 3) * 128 + tid];
#pragma unroll
        for (int r = 0; r < HEAD_ROWS; ++r) {
            float4 hv = *(const float4*)&sh[r * HDIM + k];
            acc[r] = fmaf(hv.x, w0, fmaf(hv.y, w1, fmaf(hv.z, w2, fmaf(hv.w, w3, acc[r]))));
        }
    }
    __syncthreads();

    float* so = sh;
    if (tid < 121) {
#pragma unroll
        for (int r = 0; r < HEAD_ROWS; ++r) so[r * 129 + tid] = acc[r];
    }
    __syncthreads();

    if (tid < HEAD_ROWS) {
        float m = -1e30f;
#pragma unroll
        for (int g = 0; g < GMIX; ++g) m = fmaxf(m, so[tid * 129 + 1 + g]);
        float e[GMIX]; float ssum = 0.0f;
#pragma unroll
        for (int g = 0; g < GMIX; ++g) { e[g] = expf(so[tid * 129 + 1 + g] - m); ssum += e[g]; }
        float inv = 1.0f / ssum;
#pragma unroll
        for (int g = 0; g < GMIX; ++g) so[tid * 129 + 1 + g] = e[g] * inv;
    }
    __syncthreads();

    const size_t TB  = (size_t)TB_ROWS;
    const size_t TBG = TB * GMIX;
    float* es  = out;
    float* pis = out + TB;
    float* mu1 = pis + TBG;
    float* mu2 = mu1 + TBG;
    float* s1  = mu2 + TBG;
    float* s2  = s1 + TBG;
    float* rho = s2 + TBG;

    if (tid < HEAD_ROWS)
        es[r0 + tid] = 1.0f / (1.0f + expf(so[tid * 129 + 0]));

    for (int idx = tid; idx < HEAD_ROWS * GMIX; idx += HEAD_THREADS) {
        int r = idx / GMIX, g = idx % GMIX;
        size_t off = (size_t)(r0 + r) * GMIX + g;
        pis[off] = so[r * 129 + 1 + g];
        mu1[off] = so[r * 129 + 21 + g];
        mu2[off] = so[r * 129 + 41 + g];
        s1[off]  = expf(so[r * 129 + 61 + g]);
        s2[off]  = expf(so[r * 129 + 81 + g]);
        rho[off] = tanhf(so[r * 129 + 101 + g]);
    }
}

// ---------------------------------------------------------------------------
// Launch
// ---------------------------------------------------------------------------
extern "C" void kernel_launch(void* const* d_in, const int* in_sizes, int n_in,
                              void* d_out, int out_size) {
    (void)in_sizes; (void)n_in; (void)out_size;
    const float* x     = (const float*)d_in[0];
    const float* cg    = (const float*)d_in[1];
    const float* W1ih  = (const float*)d_in[2];
    const float* W1hh  = (const float*)d_in[3];
    const float* b1    = (const float*)d_in[4];
    const float* W2ih  = (const float*)d_in[5];
    const float* W2hh  = (const float*)d_in[6];
    const float* b2    = (const float*)d_in[7];
    const float* W3ih  = (const float*)d_in[8];
    const float* W3hh  = (const float*)d_in[9];
    const float* b3    = (const float*)d_in[10];
    const float* Ww    = (const float*)d_in[11];
    const float* bw    = (const float*)d_in[12];
    const float* We    = (const float*)d_in[13];
    const float* be    = (const float*)d_in[14];
    const float* Wpi   = (const float*)d_in[15];
    const float* bpi   = (const float*)d_in[16];
    const float* Wm1   = (const float*)d_in[17];
    const float* bm1   = (const float*)d_in[18];
    const float* Wm2   = (const float*)d_in[19];
    const float* bm2   = (const float*)d_in[20];
    const float* Ws1   = (const float*)d_in[21];
    const float* bs1   = (const float*)d_in[22];
    const float* Ws2   = (const float*)d_in[23];
    const float* bs2   = (const float*)d_in[24];
    const float* Wr    = (const float*)d_in[25];
    const float* br    = (const float*)d_in[26];

    // flags must be zero every launch (graph replays reuse device state)
    zero_flags_kernel<<<(NGROUPS * T_STEPS * 4 + 255) / 256, 256>>>();

    build_ws_kernel<<<(NSLICE * NK4_1  * 512) / 256, 256>>>(W1ih, W1hh, 3 + ADIM, K1, NK4_1, 0);
    build_ws_kernel<<<(NSLICE * NK4_23 * 512) / 256, 256>>>(W2ih, W2hh, 3 + ADIM + HDIM, K23, NK4_23, 1);
    build_ws_kernel<<<(NSLICE * NK4_23 * 512) / 256, 256>>>(W3ih, W3hh, 3 + ADIM + HDIM, K23, NK4_23, 2);
    build_bias_kernel<<<(3 * NSLICE * 128 + 255) / 256, 256>>>(b1, b2, b3);
    build_head_kernel<<<(HDIM * 128 + 255) / 256, 256>>>(We, be, Wpi, bpi, Wm1, bm1,
                                                         Wm2, bm2, Ws1, bs1, Ws2, bs2, Wr, br);

    static bool attr_set = false;
    int smem_bytes = (int)sizeof(SmemR);
    if (!attr_set) {
        cudaFuncSetAttribute(rnn_kernel, cudaFuncAttributeMaxDynamicSharedMemorySize,
                             smem_bytes);
        attr_set = true;
    }
    rnn_kernel<<<RNN_CTAS, RNN_THREADS, smem_bytes>>>(x, cg, Ww, bw);

    head_kernel<<<TB_ROWS / HEAD_ROWS, HEAD_THREADS>>>((float*)d_out);
}

// round 6
// speedup vs baseline: 2.6263x; 2.0768x over previous
#include <cuda_runtime.h>
#include <math.h>
#include <stdint.h>

// ---------------------------------------------------------------------------
// Model constants
// ---------------------------------------------------------------------------
#define T_STEPS 800
#define BATCH   128
#define UDIM    64
#define ADIM    64
#define HDIM    256
#define KMIX    10
#define GMIX    20

#define K1  323               // layer1 gemv depth: x(3)+w(64)+h1(256)
#define K23 579               // layer2/3 depth:    x(3)+w(64)+h(256)+h(256)
#define NK4_1  88             // 88*4 = 352 >= 323, divisible by 8
#define NK4_23 152            // 152*4 = 608 >= 579, divisible by 8
#define KP1  (NK4_1 * 4)
#define KP23 (NK4_23 * 4)

#define NSLICE  8             // gate slices per batch group
#define NBATCH  8             // batches per group
#define NGROUPS (BATCH / NBATCH)   // 16
#define UNITS   32            // hidden units per slice
#define RNN_THREADS 256
#define RNN_CTAS (NGROUPS * NSLICE)   // 128 CTAs, one wave

#define HEAD_ROWS 32
#define HEAD_THREADS 128
#define TB_ROWS (T_STEPS * BATCH)

// packed f32x2 helpers (FFMA2 is PTX-only; ptxas never auto-fuses)
#define FMA2(d, a, b, c) \
    asm("fma.rn.f32x2 %0, %1, %2, %3;" : "=l"(d) : "l"(a), "l"(b), "l"(c))
#define PACK2(d, s) \
    asm("mov.b64 %0, {%1, %1};" : "=l"(d) : "r"(__float_as_uint(s)))

// ---------------------------------------------------------------------------
// Device scratch (static __device__ — no allocations allowed)
// ---------------------------------------------------------------------------
__device__ float g_W1[NSLICE * NK4_1  * 512];   // [slice][k4][m][kk] (float4 per (k4,m))
__device__ float g_W2[NSLICE * NK4_23 * 512];
__device__ float g_W3[NSLICE * NK4_23 * 512];
__device__ float g_B[3 * NSLICE * 128];
__device__ float g_hx[NGROUPS][3][HDIM][NBATCH];
__device__ float g_wx[NGROUPS][ADIM][NBATCH];
__device__ int   g_flags[NGROUPS * T_STEPS * 4];
__device__ float g_WHt[HDIM * 128];
__device__ float g_bh[128];
__device__ float g_h3buf[(size_t)T_STEPS * BATCH * HDIM];

// ---------------------------------------------------------------------------
// Prologue kernels
// ---------------------------------------------------------------------------
__global__ void zero_flags_kernel() {
    int i = blockIdx.x * blockDim.x + threadIdx.x;
    if (i < NGROUPS * T_STEPS * 4) g_flags[i] = 0;
}

__global__ void build_ws_kernel(const float* __restrict__ Wih,
                                const float* __restrict__ Whh,
                                int INdim, int Ktot, int nk4, int layer) {
    int idx = blockIdx.x * blockDim.x + threadIdx.x;
    int per = nk4 * 512;
    if (idx >= NSLICE * per) return;
    int r   = idx / per;
    int rem = idx % per;
    int k4  = rem >> 9;
    int q   = rem & 511;
    int m   = q >> 2;
    int kk  = q & 3;
    int k   = k4 * 4 + kk;
    int row = (m >> 5) * 256 + r * UNITS + (m & 31);
    float v = 0.0f;
    if (k < INdim)      v = Wih[row * INdim + k];
    else if (k < Ktot)  v = Whh[row * HDIM + (k - INdim)];
    float* dst = (layer == 0) ? g_W1 : (layer == 1) ? g_W2 : g_W3;
    dst[idx] = v;
}

__global__ void build_bias_kernel(const float* b1, const float* b2, const float* b3) {
    int idx = blockIdx.x * blockDim.x + threadIdx.x;
    if (idx >= 3 * NSLICE * 128) return;
    int layer = idx / (NSLICE * 128);
    int rem   = idx % (NSLICE * 128);
    int r     = rem / 128;
    int m     = rem % 128;
    int row   = (m >> 5) * 256 + r * UNITS + (m & 31);
    const float* b = (layer == 0) ? b1 : (layer == 1) ? b2 : b3;
    g_B[idx] = b[row];
}

__global__ void build_head_kernel(const float* We,  const float* be,
                                  const float* Wpi, const float* bpi,
                                  const float* Wm1, const float* bm1,
                                  const float* Wm2, const float* bm2,
                                  const float* Ws1, const float* bs1,
                                  const float* Ws2, const float* bs2,
                                  const float* Wr,  const float* br) {
    int idx = blockIdx.x * blockDim.x + threadIdx.x;
    if (idx >= HDIM * 128) return;
    int k = idx >> 7;
    int o = idx & 127;
    const float* W = nullptr; const float* bb = nullptr; int row = 0;
    if (o == 0)        { W = We;  bb = be;  row = 0; }
    else if (o <= 20)  { W = Wpi; bb = bpi; row = o - 1; }
    else if (o <= 40)  { W = Wm1; bb = bm1; row = o - 21; }
    else if (o <= 60)  { W = Wm2; bb = bm2; row = o - 41; }
    else if (o <= 80)  { W = Ws1; bb = bs1; row = o - 61; }
    else if (o <= 100) { W = Ws2; bb = bs2; row = o - 81; }
    else if (o <= 120) { W = Wr;  bb = br;  row = o - 101; }
    g_WHt[k * 128 + o] = W ? W[row * HDIM + k] : 0.0f;
    if (k == 0) g_bh[o] = bb ? bb[row] : 0.0f;
}

// ---------------------------------------------------------------------------
// Recurrent kernel smem
// ---------------------------------------------------------------------------
#define WW_STRIDE 268
#define H1T_STRIDE 260

struct __align__(16) SmemR {
    float vin1[KP1  * NBATCH];     // [k][b]
    float vin2[KP23 * NBATCH];
    float vin3[KP23 * NBATCH];
    float zpart[8 * 128 * NBATCH]; // per-warp partial sums [w][m][b]   (32 KB)
    float z[128 * NBATCH];         // reduced gates [m][b]
    float c1[UNITS * NBATCH];      // [u*8+b]
    float c2[UNITS * NBATCH];
    float c3[UNITS * NBATCH];
    float cm[UDIM * 64];           // [u][b*8+a]
    float Wws[30 * WW_STRIDE];
    float h1t[NBATCH * H1T_STRIDE];
    float bws[32];
    float b1s[128], b2s[128], b3s[128];
    float atts[32 * NBATCH];
    float kappas[KMIX * NBATCH];
    float phis[UDIM * NBATCH];
};

__device__ __forceinline__ float sigm(float v) { return 1.0f / (1.0f + __expf(-v)); }

__device__ __forceinline__ void group_barrier(int g, int t, int site) {
    __threadfence();
    __syncthreads();
    if (threadIdx.x == 0) {
        int* f = &g_flags[((g * T_STEPS) + t) * 4 + site];
        atomicAdd(f, 1);
        while (*((volatile int*)f) < NSLICE) { }
    }
    __syncthreads();
}

// k-sliced GEMV: warp w handles k4 in [w*nk4/8, (w+1)*nk4/8) for ALL 128m x 8b.
// Lane owns m = {lane, lane+32, lane+64, lane+96}, all 8 batches as 4 f32x2.
// Writes partials to zpart[w][m][b].
__device__ __forceinline__ void gemv_ws(const float* __restrict__ W,
                                        const float* __restrict__ vin,
                                        float* __restrict__ zpart,
                                        int nk4) {
    const int lane = threadIdx.x & 31;
    const int warp = threadIdx.x >> 5;
    const int per  = nk4 >> 3;
    const int kb   = warp * per;
    const int ke   = kb + per;

    unsigned long long acc[4][4];
#pragma unroll
    for (int j = 0; j < 4; ++j)
#pragma unroll
        for (int p = 0; p < 4; ++p) acc[j][p] = 0ULL;

    const float4* Wp = (const float4*)W + (size_t)kb * 128 + lane;
    float4 w0 = Wp[0], w1 = Wp[32], w2 = Wp[64], w3 = Wp[96];

    for (int k4 = kb; k4 < ke; ++k4) {
        float4 cw[4] = { w0, w1, w2, w3 };
        if (k4 + 1 < ke) {
            Wp += 128;
            w0 = Wp[0]; w1 = Wp[32]; w2 = Wp[64]; w3 = Wp[96];
        }
        const ulonglong2* V = (const ulonglong2*)(vin + k4 * 32);
#pragma unroll
        for (int kk = 0; kk < 4; ++kk) {
            ulonglong2 va = V[kk * 2];
            ulonglong2 vb = V[kk * 2 + 1];
#pragma unroll
            for (int j = 0; j < 4; ++j) {
                float wjk = ((const float*)&cw[j])[kk];
                unsigned long long wp;
                PACK2(wp, wjk);
                FMA2(acc[j][0], wp, va.x, acc[j][0]);
                FMA2(acc[j][1], wp, va.y, acc[j][1]);
                FMA2(acc[j][2], wp, vb.x, acc[j][2]);
                FMA2(acc[j][3], wp, vb.y, acc[j][3]);
            }
        }
    }
#pragma unroll
    for (int j = 0; j < 4; ++j) {
        int m = lane + 32 * j;
        unsigned long long* zp = (unsigned long long*)&zpart[(warp * 128 + m) * NBATCH];
#pragma unroll
        for (int p = 0; p < 4; ++p) zp[p] = acc[j][p];
    }
}

// reduce zpart over 8 warps, add bias -> z[m][b]
__device__ __forceinline__ void gemv_reduce(const float* __restrict__ zpart,
                                            const float* __restrict__ bias,
                                            float* __restrict__ z) {
    const int tid = threadIdx.x;
    const int m = tid >> 1, q = tid & 1;
    float b = bias[m];
    float4 acc = make_float4(b, b, b, b);
#pragma unroll
    for (int w = 0; w < 8; ++w) {
        float4 p = *(const float4*)&zpart[(w * 128 + m) * NBATCH + q * 4];
        acc.x += p.x; acc.y += p.y; acc.z += p.z; acc.w += p.w;
    }
    *(float4*)&z[m * NBATCH + q * 4] = acc;
}

// LSTM cell for 32 units x 8 batches; z layout [m][b]
__device__ __forceinline__ float cell_update(const float* __restrict__ z,
                                             float* __restrict__ c_s,
                                             float (*hx)[NBATCH], int r) {
    const int tid = threadIdx.x;
    const int u = tid >> 3, b = tid & 7;
    float zi = z[(u)      * NBATCH + b];
    float zf = z[(32 + u) * NBATCH + b];
    float zg = z[(64 + u) * NBATCH + b];
    float zo = z[(96 + u) * NBATCH + b];
    float c  = sigm(zf) * c_s[tid] + sigm(zi) * tanhf(zg);
    c_s[tid] = c;
    float h  = sigm(zo) * tanhf(c);
    hx[r * UNITS + u][b] = h;
    return h;
}

extern __shared__ char smem_raw[];

__global__ void __launch_bounds__(RNN_THREADS, 1)
rnn_kernel(const float* __restrict__ x,    // [T, B, 3]
           const float* __restrict__ cg,   // [B, U, A]
           const float* __restrict__ Ww,   // [30, 256]
           const float* __restrict__ bw)   // [30]
{
    SmemR* s = (SmemR*)smem_raw;
    const int tid = threadIdx.x;
    const int g   = blockIdx.x >> 3;
    const int r   = blockIdx.x & 7;
    const int b0  = g * NBATCH;

    // ---- init ----
    for (int i = tid; i < 30 * 256; i += RNN_THREADS) {
        int o = i >> 8, k = i & 255;
        s->Wws[o * WW_STRIDE + k] = Ww[o * 256 + k];
    }
    if (tid < 32) s->bws[tid] = (tid < 30) ? bw[tid] : 0.0f;
    if (tid < 128) {
        s->b1s[tid] = g_B[(0 * NSLICE + r) * 128 + tid];
        s->b2s[tid] = g_B[(1 * NSLICE + r) * 128 + tid];
        s->b3s[tid] = g_B[(2 * NSLICE + r) * 128 + tid];
    }
    for (int i = tid; i < UDIM * 64; i += RNN_THREADS) {
        int u = i >> 6, q = i & 63, b = q >> 3, a = q & 7;
        s->cm[i] = cg[(size_t)(b0 + b) * (UDIM * ADIM) + u * ADIM + (r * 8 + a)];
    }
    for (int i = tid; i < KP1 * NBATCH; i += RNN_THREADS) s->vin1[i] = 0.0f;
    for (int i = tid; i < KP23 * NBATCH; i += RNN_THREADS) { s->vin2[i] = 0.0f; s->vin3[i] = 0.0f; }
    __syncthreads();
    for (int i = tid; i < ADIM * NBATCH; i += RNN_THREADS) {
        s->vin1[24 + i] = 1.0f; s->vin2[24 + i] = 1.0f; s->vin3[24 + i] = 1.0f;
    }
    s->c1[tid] = 0.0f; s->c2[tid] = 0.0f; s->c3[tid] = 0.0f;
    if (tid < KMIX * NBATCH) s->kappas[tid] = 0.0f;
    __syncthreads();

    const float* W1 = g_W1 + r * (NK4_1  * 512);
    const float* W2 = g_W2 + r * (NK4_23 * 512);
    const float* W3 = g_W3 + r * (NK4_23 * 512);

    for (int t = 0; t < T_STEPS; ++t) {
        if (tid < 24) {
            int b = tid / 3, k = tid % 3;
            float xv = x[((size_t)t * BATCH + b0 + b) * 3 + k];
            s->vin1[k * 8 + b] = xv; s->vin2[k * 8 + b] = xv; s->vin3[k * 8 + b] = xv;
        }
        __syncthreads();

        // ---- layer 1 ----
        gemv_ws(W1, s->vin1, s->zpart, NK4_1);
        __syncthreads();
        gemv_reduce(s->zpart, s->b1s, s->z);
        __syncthreads();
        cell_update(s->z, s->c1, g_hx[g][0], r);
        group_barrier(g, t, 0);
        for (int i = tid; i < HDIM * NBATCH; i += RNN_THREADS) {
            int u = i >> 3, b = i & 7;
            float h = __ldcg(&g_hx[g][0][u][b]);
            s->vin1[536 + i] = h;
            s->vin2[536 + i] = h;
            s->h1t[b * H1T_STRIDE + u] = h;
        }
        __syncthreads();

        // ---- attention ----
        if (tid < 240) {
            int o = tid >> 3, b = tid & 7;
            const float4* wr = (const float4*)(s->Wws + o * WW_STRIDE);
            const float4* hv = (const float4*)(s->h1t + b * H1T_STRIDE);
            float acc = s->bws[o];
#pragma unroll 4
            for (int k4 = 0; k4 < 64; ++k4) {
                float4 wv = wr[k4], hh = hv[k4];
                acc = fmaf(wv.x, hh.x, acc); acc = fmaf(wv.y, hh.y, acc);
                acc = fmaf(wv.z, hh.z, acc); acc = fmaf(wv.w, hh.w, acc);
            }
            s->atts[o * 8 + b] = __expf(acc);
        }
        __syncthreads();
        if (tid < KMIX * NBATCH) {
            int kk = tid >> 3, b = tid & 7;
            s->kappas[tid] += 0.1f * s->atts[(20 + kk) * 8 + b];
        }
        __syncthreads();
        for (int i = tid; i < UDIM * NBATCH; i += RNN_THREADS) {
            int u = i >> 3, b = i & 7;
            float uu = (float)u;
            float acc = 0.0f;
#pragma unroll
            for (int kk = 0; kk < KMIX; ++kk) {
                float d = s->kappas[kk * 8 + b] - uu;
                acc = fmaf(s->atts[kk * 8 + b],
                           __expf(-s->atts[(10 + kk) * 8 + b] * d * d), acc);
            }
            s->phis[i] = acc;
        }
        __syncthreads();
        if (tid < 64) {
            int b = tid >> 3, a = tid & 7;
            float acc = 0.0f;
#pragma unroll 8
            for (int u = 0; u < UDIM; ++u)
                acc = fmaf(s->phis[u * 8 + b], s->cm[u * 64 + b * 8 + a], acc);
            g_wx[g][r * 8 + a][b] = acc;
        }
        group_barrier(g, t, 1);
        for (int i = tid; i < ADIM * NBATCH; i += RNN_THREADS) {
            int a = i >> 3, b = i & 7;
            float wv = __ldcg(&g_wx[g][a][b]);
            s->vin1[24 + i] = wv; s->vin2[24 + i] = wv; s->vin3[24 + i] = wv;
        }
        __syncthreads();

        // ---- layer 2 ----
        gemv_ws(W2, s->vin2, s->zpart, NK4_23);
        __syncthreads();
        gemv_reduce(s->zpart, s->b2s, s->z);
        __syncthreads();
        cell_update(s->z, s->c2, g_hx[g][1], r);
        group_barrier(g, t, 2);
        for (int i = tid; i < HDIM * NBATCH; i += RNN_THREADS) {
            float h = __ldcg(&g_hx[g][1][i >> 3][i & 7]);
            s->vin3[536 + i]  = h;
            s->vin2[2584 + i] = h;
        }
        __syncthreads();

        // ---- layer 3 ----
        gemv_ws(W3, s->vin3, s->zpart, NK4_23);
        __syncthreads();
        gemv_reduce(s->zpart, s->b3s, s->z);
        __syncthreads();
        {
            float h = cell_update(s->z, s->c3, g_hx[g][2], r);
            int u = tid >> 3, b = tid & 7;
            g_h3buf[((size_t)t * BATCH + b0 + b) * HDIM + r * UNITS + u] = h;
        }
        group_barrier(g, t, 3);
        for (int i = tid; i < HDIM * NBATCH; i += RNN_THREADS)
            s->vin3[2584 + i] = __ldcg(&g_hx[g][2][i >> 3][i & 7]);
        __syncthreads();
    }
}

// ---------------------------------------------------------------------------
// Output head
// ---------------------------------------------------------------------------
__global__ void __launch_bounds__(HEAD_THREADS)
head_kernel(float* __restrict__ out) {
    __shared__ float sh[HEAD_ROWS * HDIM];
    const int tid = threadIdx.x;
    const int r0  = blockIdx.x * HEAD_ROWS;

    for (int i = tid; i < HEAD_ROWS * HDIM; i += HEAD_THREADS)
        sh[i] = g_h3buf[(size_t)r0 * HDIM + i];
    __syncthreads();

    float acc[HEAD_ROWS];
    float bias = g_bh[tid];
#pragma unroll
    for (int r = 0; r < HEAD_ROWS; ++r) acc[r] = bias;

    for (int k = 0; k < HDIM; k += 4) {
        float w0 = g_WHt[(k + 0) * 128 + tid];
        float w1 = g_WHt[(k + 1) * 128 + tid];
        float w2 = g_WHt[(k + 2) * 128 + tid];
        float w3 = g_WHt[(k + 3) * 128 + tid];
#pragma unroll
        for (int r = 0; r < HEAD_ROWS; ++r) {
            float4 hv = *(const float4*)&sh[r * HDIM + k];
            acc[r] = fmaf(hv.x, w0, fmaf(hv.y, w1, fmaf(hv.z, w2, fmaf(hv.w, w3, acc[r]))));
        }
    }
    __syncthreads();

    float* so = sh;
    if (tid < 121) {
#pragma unroll
        for (int r = 0; r < HEAD_ROWS; ++r) so[r * 129 + tid] = acc[r];
    }
    __syncthreads();

    if (tid < HEAD_ROWS) {
        float m = -1e30f;
#pragma unroll
        for (int g = 0; g < GMIX; ++g) m = fmaxf(m, so[tid * 129 + 1 + g]);
        float e[GMIX]; float ssum = 0.0f;
#pragma unroll
        for (int g = 0; g < GMIX; ++g) { e[g] = expf(so[tid * 129 + 1 + g] - m); ssum += e[g]; }
        float inv = 1.0f / ssum;
#pragma unroll
        for (int g = 0; g < GMIX; ++g) so[tid * 129 + 1 + g] = e[g] * inv;
    }
    __syncthreads();

    const size_t TB  = (size_t)TB_ROWS;
    const size_t TBG = TB * GMIX;
    float* es  = out;
    float* pis = out + TB;
    float* mu1 = pis + TBG;
    float* mu2 = mu1 + TBG;
    float* s1  = mu2 + TBG;
    float* s2  = s1 + TBG;
    float* rho = s2 + TBG;

    if (tid < HEAD_ROWS)
        es[r0 + tid] = 1.0f / (1.0f + expf(so[tid * 129 + 0]));

    for (int idx = tid; idx < HEAD_ROWS * GMIX; idx += HEAD_THREADS) {
        int r = idx / GMIX, g = idx % GMIX;
        size_t off = (size_t)(r0 + r) * GMIX + g;
        pis[off] = so[r * 129 + 1 + g];
        mu1[off] = so[r * 129 + 21 + g];
        mu2[off] = so[r * 129 + 41 + g];
        s1[off]  = expf(so[r * 129 + 61 + g]);
        s2[off]  = expf(so[r * 129 + 81 + g]);
        rho[off] = tanhf(so[r * 129 + 101 + g]);
    }
}

// ---------------------------------------------------------------------------
// Launch
// ---------------------------------------------------------------------------
extern "C" void kernel_launch(void* const* d_in, const int* in_sizes, int n_in,
                              void* d_out, int out_size) {
    (void)in_sizes; (void)n_in; (void)out_size;
    const float* x     = (const float*)d_in[0];
    const float* cg    = (const float*)d_in[1];
    const float* W1ih  = (const float*)d_in[2];
    const float* W1hh  = (const float*)d_in[3];
    const float* b1    = (const float*)d_in[4];
    const float* W2ih  = (const float*)d_in[5];
    const float* W2hh  = (const float*)d_in[6];
    const float* b2    = (const float*)d_in[7];
    const float* W3ih  = (const float*)d_in[8];
    const float* W3hh  = (const float*)d_in[9];
    const float* b3    = (const float*)d_in[10];
    const float* Ww    = (const float*)d_in[11];
    const float* bw    = (const float*)d_in[12];
    const float* We    = (const float*)d_in[13];
    const float* be    = (const float*)d_in[14];
    const float* Wpi   = (const float*)d_in[15];
    const float* bpi   = (const float*)d_in[16];
    const float* Wm1   = (const float*)d_in[17];
    const float* bm1   = (const float*)d_in[18];
    const float* Wm2   = (const float*)d_in[19];
    const float* bm2   = (const float*)d_in[20];
    const float* Ws1   = (const float*)d_in[21];
    const float* bs1   = (const float*)d_in[22];
    const float* Ws2   = (const float*)d_in[23];
    const float* bs2   = (const float*)d_in[24];
    const float* Wr    = (const float*)d_in[25];
    const float* br    = (const float*)d_in[26];

    zero_flags_kernel<<<(NGROUPS * T_STEPS * 4 + 255) / 256, 256>>>();

    build_ws_kernel<<<(NSLICE * NK4_1  * 512) / 256, 256>>>(W1ih, W1hh, 3 + ADIM, K1, NK4_1, 0);
    build_ws_kernel<<<(NSLICE * NK4_23 * 512) / 256, 256>>>(W2ih, W2hh, 3 + ADIM + HDIM, K23, NK4_23, 1);
    build_ws_kernel<<<(NSLICE * NK4_23 * 512) / 256, 256>>>(W3ih, W3hh, 3 + ADIM + HDIM, K23, NK4_23, 2);
    build_bias_kernel<<<(3 * NSLICE * 128 + 255) / 256, 256>>>(b1, b2, b3);
    build_head_kernel<<<(HDIM * 128 + 255) / 256, 256>>>(We, be, Wpi, bpi, Wm1, bm1,
                                                         Wm2, bm2, Ws1, bs1, Ws2, bs2, Wr, br);

    static bool attr_set = false;
    int smem_bytes = (int)sizeof(SmemR);
    if (!attr_set) {
        cudaFuncSetAttribute(rnn_kernel, cudaFuncAttributeMaxDynamicSharedMemorySize,
                             smem_bytes);
        attr_set = true;
    }
    rnn_kernel<<<RNN_CTAS, RNN_THREADS, smem_bytes>>>(x, cg, Ww, bw);

    head_kernel<<<TB_ROWS / HEAD_ROWS, HEAD_THREADS>>>((float*)d_out);
}